// round 2
// baseline (speedup 1.0000x reference)
#include <cuda_runtime.h>
#include <math.h>

// Problem constants
#define B_    2
#define S_    2048
#define D_    1024
#define H_    16
#define DH_   64
#define M_TOT (B_ * S_)      // 4096
#define QKV_N (3 * D_)       // 3072
#define SCALE 0.125f         // 1/sqrt(64)

// Scratch buffers (allocation-free rule: __device__ globals)
__device__ float g_qkv[M_TOT * QKV_N];   // (B*S, 3*D)  ~50 MB
__device__ float g_att[M_TOT * D_];      // (B*S, D)    ~17 MB

// ---------------------------------------------------------------------------
// GEMM: C[M,N] = A[M,K] @ B[N,K]^T   (both row-major; matches x @ W.T)
// 128x128 block tile, BK=16, 256 threads, 8x8 micro-tile per thread.
// ---------------------------------------------------------------------------
__global__ __launch_bounds__(256) void gemm_nt_kernel(
    const float* __restrict__ A,
    const float* __restrict__ Bm,
    float* __restrict__ C,
    int N, int K)
{
    const int BM = 128, BN = 128, BK = 16;
    __shared__ float Ast[16][132];   // [k][m], padded
    __shared__ float Bst[16][132];   // [k][n], padded

    const int t  = threadIdx.x;
    const int bm = blockIdx.y * BM;
    const int bn = blockIdx.x * BN;
    const int m0 = (t >> 4) * 8;
    const int n0 = (t & 15) * 8;

    float acc[8][8];
    #pragma unroll
    for (int i = 0; i < 8; i++)
        #pragma unroll
        for (int j = 0; j < 8; j++) acc[i][j] = 0.0f;

    for (int k0 = 0; k0 < K; k0 += BK) {
        // Cooperative load: 128x16 of A and of B, float4 per 4 k's
        #pragma unroll
        for (int u = 0; u < 2; u++) {
            int idx = t + 256 * u;          // 0..511
            int row = idx >> 2;             // 0..127
            int kq  = (idx & 3) * 4;        // 0,4,8,12
            float4 av = *(const float4*)(A + (size_t)(bm + row) * K + k0 + kq);
            Ast[kq + 0][row] = av.x; Ast[kq + 1][row] = av.y;
            Ast[kq + 2][row] = av.z; Ast[kq + 3][row] = av.w;
            float4 bv = *(const float4*)(Bm + (size_t)(bn + row) * K + k0 + kq);
            Bst[kq + 0][row] = bv.x; Bst[kq + 1][row] = bv.y;
            Bst[kq + 2][row] = bv.z; Bst[kq + 3][row] = bv.w;
        }
        __syncthreads();

        #pragma unroll
        for (int kk = 0; kk < BK; kk++) {
            float4 a0 = *(const float4*)&Ast[kk][m0];
            float4 a1 = *(const float4*)&Ast[kk][m0 + 4];
            float4 b0 = *(const float4*)&Bst[kk][n0];
            float4 b1 = *(const float4*)&Bst[kk][n0 + 4];
            float a[8] = {a0.x, a0.y, a0.z, a0.w, a1.x, a1.y, a1.z, a1.w};
            float b[8] = {b0.x, b0.y, b0.z, b0.w, b1.x, b1.y, b1.z, b1.w};
            #pragma unroll
            for (int i = 0; i < 8; i++)
                #pragma unroll
                for (int j = 0; j < 8; j++)
                    acc[i][j] = fmaf(a[i], b[j], acc[i][j]);
        }
        __syncthreads();
    }

    // Epilogue
    #pragma unroll
    for (int i = 0; i < 8; i++) {
        float* crow = C + (size_t)(bm + m0 + i) * N + bn + n0;
        float4 v0 = make_float4(acc[i][0], acc[i][1], acc[i][2], acc[i][3]);
        float4 v1 = make_float4(acc[i][4], acc[i][5], acc[i][6], acc[i][7]);
        *(float4*)(crow + 0) = v0;
        *(float4*)(crow + 4) = v1;
    }
}

// ---------------------------------------------------------------------------
// Flash attention: per (b,h), 64-query tiles over 32 key-tiles of 64.
// Online softmax: running max == stop_gradient(max); denom l + 1e-6 matches
// reference; the [-50,50] clip affects only terms <= e^-50 (below fp32 eps).
// Grid: (32 q-tiles, 32 b*h). 256 threads, 16x16 layout, 4x4 per thread.
// ---------------------------------------------------------------------------
__global__ __launch_bounds__(256) void flash_attn_kernel()
{
    extern __shared__ float sm[];
    float* Qs = sm;                 // [64][65]
    float* Ks = sm + 4160;          // [64][65]
    float* Vs = sm + 8320;          // [64][65]
    float* Ps = sm + 12480;         // [64][65]

    const int t  = threadIdx.x;
    const int qt = blockIdx.x;          // 0..31
    const int bh = blockIdx.y;          // 0..31
    const int b  = bh >> 4;
    const int h  = bh & 15;

    const float* qbase = g_qkv + (size_t)(b * S_ + qt * 64) * QKV_N + 0 * D_ + h * DH_;
    const float* kbase = g_qkv + (size_t)(b * S_) * QKV_N + 1 * D_ + h * DH_;
    const float* vbase = g_qkv + (size_t)(b * S_) * QKV_N + 2 * D_ + h * DH_;

    // Load Q tile (64 rows x 64 dims)
    for (int idx = t; idx < 64 * 16; idx += 256) {
        int row = idx >> 4;
        int dq  = (idx & 15) * 4;
        float4 v = *(const float4*)(qbase + (size_t)row * QKV_N + dq);
        Qs[row * 65 + dq + 0] = v.x; Qs[row * 65 + dq + 1] = v.y;
        Qs[row * 65 + dq + 2] = v.z; Qs[row * 65 + dq + 3] = v.w;
    }

    const int ty = t >> 4, tx = t & 15;
    const int r0 = ty * 4, c0 = tx * 4;

    float m[4], l[4], O[4][4];
    #pragma unroll
    for (int i = 0; i < 4; i++) {
        m[i] = -1e30f; l[i] = 0.0f;
        #pragma unroll
        for (int j = 0; j < 4; j++) O[i][j] = 0.0f;
    }

    for (int kt = 0; kt < S_ / 64; kt++) {
        __syncthreads();   // prior-iter reads of Ks/Vs/Ps done (also covers Q load)
        // Load K,V tiles
        for (int idx = t; idx < 64 * 16; idx += 256) {
            int row = idx >> 4;
            int dq  = (idx & 15) * 4;
            size_t goff = (size_t)(kt * 64 + row) * QKV_N + dq;
            float4 kv = *(const float4*)(kbase + goff);
            Ks[row * 65 + dq + 0] = kv.x; Ks[row * 65 + dq + 1] = kv.y;
            Ks[row * 65 + dq + 2] = kv.z; Ks[row * 65 + dq + 3] = kv.w;
            float4 vv = *(const float4*)(vbase + goff);
            Vs[row * 65 + dq + 0] = vv.x; Vs[row * 65 + dq + 1] = vv.y;
            Vs[row * 65 + dq + 2] = vv.z; Vs[row * 65 + dq + 3] = vv.w;
        }
        __syncthreads();

        // S = Q @ K^T (4x4 per thread)
        float s[4][4];
        #pragma unroll
        for (int i = 0; i < 4; i++)
            #pragma unroll
            for (int j = 0; j < 4; j++) s[i][j] = 0.0f;

        #pragma unroll 4
        for (int d = 0; d < 64; d++) {
            float q0 = Qs[(r0 + 0) * 65 + d];
            float q1 = Qs[(r0 + 1) * 65 + d];
            float q2 = Qs[(r0 + 2) * 65 + d];
            float q3 = Qs[(r0 + 3) * 65 + d];
            float k0 = Ks[(c0 + 0) * 65 + d];
            float k1 = Ks[(c0 + 1) * 65 + d];
            float k2 = Ks[(c0 + 2) * 65 + d];
            float k3 = Ks[(c0 + 3) * 65 + d];
            s[0][0] = fmaf(q0, k0, s[0][0]); s[0][1] = fmaf(q0, k1, s[0][1]);
            s[0][2] = fmaf(q0, k2, s[0][2]); s[0][3] = fmaf(q0, k3, s[0][3]);
            s[1][0] = fmaf(q1, k0, s[1][0]); s[1][1] = fmaf(q1, k1, s[1][1]);
            s[1][2] = fmaf(q1, k2, s[1][2]); s[1][3] = fmaf(q1, k3, s[1][3]);
            s[2][0] = fmaf(q2, k0, s[2][0]); s[2][1] = fmaf(q2, k1, s[2][1]);
            s[2][2] = fmaf(q2, k2, s[2][2]); s[2][3] = fmaf(q2, k3, s[2][3]);
            s[3][0] = fmaf(q3, k0, s[3][0]); s[3][1] = fmaf(q3, k1, s[3][1]);
            s[3][2] = fmaf(q3, k2, s[3][2]); s[3][3] = fmaf(q3, k3, s[3][3]);
        }

        // Online softmax update (per-row; 16 lanes of same ty share each row)
        #pragma unroll
        for (int i = 0; i < 4; i++) {
            #pragma unroll
            for (int j = 0; j < 4; j++) s[i][j] *= SCALE;
            float rm = fmaxf(fmaxf(s[i][0], s[i][1]), fmaxf(s[i][2], s[i][3]));
            #pragma unroll
            for (int off = 8; off > 0; off >>= 1)
                rm = fmaxf(rm, __shfl_xor_sync(0xffffffffu, rm, off));
            float mn = fmaxf(m[i], rm);
            float corr = __expf(m[i] - mn);
            l[i] *= corr;
            #pragma unroll
            for (int j = 0; j < 4; j++) O[i][j] *= corr;
            float rs = 0.0f;
            #pragma unroll
            for (int j = 0; j < 4; j++) {
                s[i][j] = __expf(s[i][j] - mn);
                rs += s[i][j];
            }
            #pragma unroll
            for (int off = 8; off > 0; off >>= 1)
                rs += __shfl_xor_sync(0xffffffffu, rs, off);
            l[i] += rs;
            m[i] = mn;
            #pragma unroll
            for (int j = 0; j < 4; j++)
                Ps[(r0 + i) * 65 + c0 + j] = s[i][j];
        }
        __syncthreads();

        // O += P @ V
        #pragma unroll 4
        for (int kk = 0; kk < 64; kk++) {
            float p0 = Ps[(r0 + 0) * 65 + kk];
            float p1 = Ps[(r0 + 1) * 65 + kk];
            float p2 = Ps[(r0 + 2) * 65 + kk];
            float p3 = Ps[(r0 + 3) * 65 + kk];
            float v0 = Vs[kk * 65 + c0 + 0];
            float v1 = Vs[kk * 65 + c0 + 1];
            float v2 = Vs[kk * 65 + c0 + 2];
            float v3 = Vs[kk * 65 + c0 + 3];
            O[0][0] = fmaf(p0, v0, O[0][0]); O[0][1] = fmaf(p0, v1, O[0][1]);
            O[0][2] = fmaf(p0, v2, O[0][2]); O[0][3] = fmaf(p0, v3, O[0][3]);
            O[1][0] = fmaf(p1, v0, O[1][0]); O[1][1] = fmaf(p1, v1, O[1][1]);
            O[1][2] = fmaf(p1, v2, O[1][2]); O[1][3] = fmaf(p1, v3, O[1][3]);
            O[2][0] = fmaf(p2, v0, O[2][0]); O[2][1] = fmaf(p2, v1, O[2][1]);
            O[2][2] = fmaf(p2, v2, O[2][2]); O[2][3] = fmaf(p2, v3, O[2][3]);
            O[3][0] = fmaf(p3, v0, O[3][0]); O[3][1] = fmaf(p3, v1, O[3][1]);
            O[3][2] = fmaf(p3, v2, O[3][2]); O[3][3] = fmaf(p3, v3, O[3][3]);
        }
    }

    // Epilogue: normalize (reference: sum + 1e-6 in denominator), write to g_att
    float* obase = g_att + (size_t)(b * S_ + qt * 64) * D_ + h * DH_;
    #pragma unroll
    for (int i = 0; i < 4; i++) {
        float inv = 1.0f / (l[i] + 1e-6f);
        #pragma unroll
        for (int j = 0; j < 4; j++)
            obase[(size_t)(r0 + i) * D_ + c0 + j] = O[i][j] * inv;
    }
}

// ---------------------------------------------------------------------------
// Launch
// ---------------------------------------------------------------------------
extern "C" void kernel_launch(void* const* d_in, const int* in_sizes, int n_in,
                              void* d_out, int out_size)
{
    const float* x    = (const float*)d_in[0];   // (2,2048,1024)
    const float* Wqkv = (const float*)d_in[1];   // (3072,1024)
    const float* Wout = (const float*)d_in[2];   // (1024,1024)
    float* out = (float*)d_out;                  // (2,2048,1024)

    float *qkv, *att;
    cudaGetSymbolAddress((void**)&qkv, g_qkv);
    cudaGetSymbolAddress((void**)&att, g_att);

    // 1) qkv = x @ Wqkv^T    (4096 x 3072, K=1024)
    gemm_nt_kernel<<<dim3(QKV_N / 128, M_TOT / 128), 256>>>(x, Wqkv, qkv, QKV_N, D_);

    // 2) attention -> g_att
    size_t smem_att = 4 * 64 * 65 * sizeof(float);  // 66,560 B
    cudaFuncSetAttribute(flash_attn_kernel,
                         cudaFuncAttributeMaxDynamicSharedMemorySize, (int)smem_att);
    flash_attn_kernel<<<dim3(S_ / 64, B_ * H_), 256, smem_att>>>();

    // 3) out = g_att @ Wout^T   (4096 x 1024, K=1024)
    gemm_nt_kernel<<<dim3(D_ / 128, M_TOT / 128), 256>>>(att, Wout, out, D_, D_);
}

// round 4
// speedup vs baseline: 2.8025x; 2.8025x over previous
#include <cuda_runtime.h>
#include <cuda_bf16.h>
#include <math.h>
#include <stdint.h>

typedef __nv_bfloat16 bf16;

// ---------------------------------------------------------------------------
// Problem constants
// ---------------------------------------------------------------------------
#define B_    2
#define S_    2048
#define D_    1024
#define H_    16
#define DH_   64
#define M_TOT (B_ * S_)      // 4096
#define QKV_N (3 * D_)       // 3072
#define K_    1024
#define SCALE 0.125f

// ---------------------------------------------------------------------------
// Scratch (__device__ globals)
// ---------------------------------------------------------------------------
__device__ bf16 g_xhi[M_TOT * D_],  g_xlo[M_TOT * D_];
__device__ bf16 g_wqhi[QKV_N * D_], g_wqlo[QKV_N * D_];
__device__ bf16 g_wohi[D_ * D_],    g_wolo[D_ * D_];
__device__ bf16 g_qhi[M_TOT * QKV_N], g_qlo[M_TOT * QKV_N];  // qkv hi/lo
__device__ bf16 g_ahi[M_TOT * D_],  g_alo[M_TOT * D_];       // attn out hi/lo

// ---------------------------------------------------------------------------
// Helpers
// ---------------------------------------------------------------------------
__device__ __forceinline__ uint32_t sptr(const void* p) {
    return (uint32_t)__cvta_generic_to_shared(p);
}
__device__ __forceinline__ void cp16(uint32_t d, const void* s) {
    asm volatile("cp.async.cg.shared.global [%0], [%1], 16;" :: "r"(d), "l"(s));
}
#define CP_COMMIT() asm volatile("cp.async.commit_group;" ::: "memory")
#define CP_WAIT(n)  asm volatile("cp.async.wait_group %0;" :: "n"(n) : "memory")

__device__ __forceinline__ void ldsm4(uint32_t a, uint32_t r[4]) {
    asm volatile("ldmatrix.sync.aligned.m8n8.x4.shared.b16 {%0,%1,%2,%3}, [%4];"
                 : "=r"(r[0]), "=r"(r[1]), "=r"(r[2]), "=r"(r[3]) : "r"(a));
}
__device__ __forceinline__ void ldsm4t(uint32_t a, uint32_t r[4]) {
    asm volatile("ldmatrix.sync.aligned.m8n8.x4.trans.shared.b16 {%0,%1,%2,%3}, [%4];"
                 : "=r"(r[0]), "=r"(r[1]), "=r"(r[2]), "=r"(r[3]) : "r"(a));
}
__device__ __forceinline__ void mma_bf16(float c[4], const uint32_t a[4],
                                         uint32_t b0, uint32_t b1) {
    asm volatile(
        "mma.sync.aligned.m16n8k16.row.col.f32.bf16.bf16.f32 "
        "{%0,%1,%2,%3}, {%4,%5,%6,%7}, {%8,%9}, {%0,%1,%2,%3};"
        : "+f"(c[0]), "+f"(c[1]), "+f"(c[2]), "+f"(c[3])
        : "r"(a[0]), "r"(a[1]), "r"(a[2]), "r"(a[3]), "r"(b0), "r"(b1));
}
// pack (a,b) -> bf16x2 hi + bf16x2 lo (residuals)
__device__ __forceinline__ void split_pack(float a, float b, uint32_t& hi, uint32_t& lo) {
    __nv_bfloat162 hp = __floats2bfloat162_rn(a, b);
    float ra = a - __bfloat162float(hp.x);
    float rb = b - __bfloat162float(hp.y);
    __nv_bfloat162 lp = __floats2bfloat162_rn(ra, rb);
    hi = *(uint32_t*)&hp;
    lo = *(uint32_t*)&lp;
}

// ---------------------------------------------------------------------------
// Split: fp32 -> bf16 hi + bf16 lo
// ---------------------------------------------------------------------------
__global__ void split_bf16(const float* __restrict__ src,
                           bf16* __restrict__ hi, bf16* __restrict__ lo, int n)
{
    for (int i = blockIdx.x * blockDim.x + threadIdx.x; i < n; i += gridDim.x * blockDim.x) {
        float v = src[i];
        bf16 h = __float2bfloat16(v);
        hi[i] = h;
        lo[i] = __float2bfloat16(v - __bfloat162float(h));
    }
}

// ---------------------------------------------------------------------------
// GEMM: C[M,N] = A[M,K=1024] @ B[N,K=1024]^T  via mma.sync bf16 (3-pass hi/lo)
// 128x128 tile, 8 warps (64x32 each), BK=32, cp.async double-buffered.
// SPLIT: write bf16 hi/lo outputs; else fp32.
// ---------------------------------------------------------------------------
#define PKB 80   // padded row stride bytes (32 bf16 + 8 pad)
#define GSTAGE 40960

template<bool SPLIT>
__global__ __launch_bounds__(256) void gemm_mma(
    const bf16* __restrict__ Ahi, const bf16* __restrict__ Alo,
    const bf16* __restrict__ Bhi, const bf16* __restrict__ Blo,
    float* __restrict__ Cf, bf16* __restrict__ Chi, bf16* __restrict__ Clo, int N)
{
    extern __shared__ char smx[];
    const int tid = threadIdx.x, lane = tid & 31, wid = tid >> 5;
    const int bm = blockIdx.y * 128, bn = blockIdx.x * 128;
    const int m0 = (wid >> 2) * 64, n0 = (wid & 3) * 32;

    const bf16* pA[2] = { Ahi + (size_t)bm * K_, Alo + (size_t)bm * K_ };
    const bf16* pB[2] = { Bhi + (size_t)bn * K_, Blo + (size_t)bn * K_ };

    float acc[4][4][4];
    #pragma unroll
    for (int i = 0; i < 4; i++)
        #pragma unroll
        for (int j = 0; j < 4; j++)
            #pragma unroll
            for (int q = 0; q < 4; q++) acc[i][j][q] = 0.0f;

    auto load_stage = [&](int s, int k0) {
        char* base = smx + s * GSTAGE;
        #pragma unroll
        for (int a2 = 0; a2 < 2; a2++) {
            #pragma unroll
            for (int i = 0; i < 2; i++) {
                int idx = tid + i * 256;          // 0..511
                int r = idx >> 2, c = idx & 3;
                cp16(sptr(base + a2 * 10240 + r * PKB + c * 16),
                     pA[a2] + (size_t)r * K_ + k0 + c * 8);
                cp16(sptr(base + 20480 + a2 * 10240 + r * PKB + c * 16),
                     pB[a2] + (size_t)r * K_ + k0 + c * 8);
            }
        }
    };

    load_stage(0, 0);
    CP_COMMIT();

    const int row_in = lane & 7, g = lane >> 3;

    for (int kc = 0; kc < K_ / 32; kc++) {
        if (kc + 1 < K_ / 32) {
            load_stage((kc + 1) & 1, (kc + 1) * 32);
            CP_COMMIT();
            CP_WAIT(1);
        } else {
            CP_WAIT(0);
        }
        __syncthreads();

        char* base = smx + (kc & 1) * GSTAGE;
        uint32_t bAh = sptr(base), bAl = bAh + 10240;
        uint32_t bBh = bAh + 20480, bBl = bAh + 30720;

        #pragma unroll
        for (int ks = 0; ks < 2; ks++) {
            uint32_t ah[4][4], al[4][4];
            #pragma unroll
            for (int mt = 0; mt < 4; mt++) {
                uint32_t off = (uint32_t)(m0 + mt * 16 + row_in + (g & 1) * 8) * PKB
                             + (ks * 16 + (g >> 1) * 8) * 2;
                ldsm4(bAh + off, ah[mt]);
                ldsm4(bAl + off, al[mt]);
            }
            uint32_t bh[2][4], bl[2][4];
            #pragma unroll
            for (int gb = 0; gb < 2; gb++) {
                uint32_t off = (uint32_t)(n0 + gb * 16 + ((g >> 1) & 1) * 8 + row_in) * PKB
                             + (ks * 16 + (g & 1) * 8) * 2;
                ldsm4(bBh + off, bh[gb]);
                ldsm4(bBl + off, bl[gb]);
            }
            #pragma unroll
            for (int mt = 0; mt < 4; mt++)
                #pragma unroll
                for (int nt = 0; nt < 4; nt++) {
                    int gb = nt >> 1, ix = (nt & 1) * 2;
                    mma_bf16(acc[mt][nt], ah[mt], bh[gb][ix], bh[gb][ix + 1]);
                    mma_bf16(acc[mt][nt], ah[mt], bl[gb][ix], bl[gb][ix + 1]);
                    mma_bf16(acc[mt][nt], al[mt], bh[gb][ix], bh[gb][ix + 1]);
                }
        }
        __syncthreads();
    }

    // Epilogue
    #pragma unroll
    for (int mt = 0; mt < 4; mt++)
        #pragma unroll
        for (int nt = 0; nt < 4; nt++) {
            int row = bm + m0 + mt * 16 + (lane >> 2);
            int col = bn + n0 + nt * 8 + (lane & 3) * 2;
            float* c = acc[mt][nt];
            if (SPLIT) {
                uint32_t h0, l0, h1, l1;
                split_pack(c[0], c[1], h0, l0);
                split_pack(c[2], c[3], h1, l1);
                *(uint32_t*)(Chi + (size_t)row * N + col) = h0;
                *(uint32_t*)(Clo + (size_t)row * N + col) = l0;
                *(uint32_t*)(Chi + (size_t)(row + 8) * N + col) = h1;
                *(uint32_t*)(Clo + (size_t)(row + 8) * N + col) = l1;
            } else {
                *(float2*)(Cf + (size_t)row * N + col) = make_float2(c[0], c[1]);
                *(float2*)(Cf + (size_t)(row + 8) * N + col) = make_float2(c[2], c[3]);
            }
        }
}

// ---------------------------------------------------------------------------
// Flash attention via mma.sync bf16 (3-pass hi/lo on QK^T and PV).
// 4 warps x 16 q-rows = 64-q tile; loop over 32 key-tiles of 64.
// Online fp32 softmax (matches reference math; see R2).
// ---------------------------------------------------------------------------
#define PDD 144   // padded row stride bytes for [.][64] bf16 tiles (64+8 elems)
// smem offsets
#define SQH 0
#define SQL 9216
#define SKH 18432
#define SKL 27648
#define SVH 36864
#define SVL 46080
#define ATT_SMEM 55296

__global__ __launch_bounds__(128) void attn_mma()
{
    extern __shared__ char smx[];
    const int tid = threadIdx.x, lane = tid & 31, warp = tid >> 5;
    const int qt = blockIdx.x;
    const int b  = blockIdx.y >> 4;
    const int h  = blockIdx.y & 15;
    const int qrow0 = b * S_ + qt * 64;

    const bf16* qh = g_qhi + (size_t)qrow0 * QKV_N + h * DH_;
    const bf16* ql = g_qlo + (size_t)qrow0 * QKV_N + h * DH_;
    const bf16* kh = g_qhi + (size_t)(b * S_) * QKV_N + D_ + h * DH_;
    const bf16* kl = g_qlo + (size_t)(b * S_) * QKV_N + D_ + h * DH_;
    const bf16* vh = g_qhi + (size_t)(b * S_) * QKV_N + 2 * D_ + h * DH_;
    const bf16* vl = g_qlo + (size_t)(b * S_) * QKV_N + 2 * D_ + h * DH_;

    uint32_t sb = sptr(smx);

    auto ld_tile = [&](const bf16* src, int smoff) {
        #pragma unroll
        for (int i = 0; i < 4; i++) {
            int idx = tid + i * 128;              // 0..511
            int r = idx >> 3, c = idx & 7;
            cp16(sb + smoff + r * PDD + c * 16, src + (size_t)r * QKV_N + c * 8);
        }
    };

    // Q tiles
    ld_tile(qh, SQH);
    ld_tile(ql, SQL);
    CP_COMMIT();
    CP_WAIT(0);
    __syncthreads();

    const int row_in = lane & 7, g = lane >> 3;

    // Q fragments (held in registers for the whole kernel)
    uint32_t qa_h[4][4], qa_l[4][4];
    #pragma unroll
    for (int ks = 0; ks < 4; ks++) {
        uint32_t off = (uint32_t)(warp * 16 + row_in + (g & 1) * 8) * PDD
                     + (ks * 16 + (g >> 1) * 8) * 2;
        ldsm4(sb + SQH + off, qa_h[ks]);
        ldsm4(sb + SQL + off, qa_l[ks]);
    }

    float m0 = -1e30f, m1 = -1e30f, l0 = 0.0f, l1 = 0.0f;
    float O[8][4];
    #pragma unroll
    for (int nt = 0; nt < 8; nt++)
        #pragma unroll
        for (int q = 0; q < 4; q++) O[nt][q] = 0.0f;

    for (int kt = 0; kt < S_ / 64; kt++) {
        int krow = kt * 64;
        ld_tile(kh + (size_t)krow * QKV_N, SKH);
        ld_tile(kl + (size_t)krow * QKV_N, SKL);
        ld_tile(vh + (size_t)krow * QKV_N, SVH);
        ld_tile(vl + (size_t)krow * QKV_N, SVL);
        CP_COMMIT();
        CP_WAIT(0);
        __syncthreads();

        // ---- S = Q @ K^T ----
        float s[8][4];
        #pragma unroll
        for (int nt = 0; nt < 8; nt++)
            #pragma unroll
            for (int q = 0; q < 4; q++) s[nt][q] = 0.0f;

        #pragma unroll
        for (int ks = 0; ks < 4; ks++) {
            uint32_t bh[4][4], bl[4][4];
            #pragma unroll
            for (int gb = 0; gb < 4; gb++) {
                uint32_t off = (uint32_t)(gb * 16 + ((g >> 1) & 1) * 8 + row_in) * PDD
                             + (ks * 16 + (g & 1) * 8) * 2;
                ldsm4(sb + SKH + off, bh[gb]);
                ldsm4(sb + SKL + off, bl[gb]);
            }
            #pragma unroll
            for (int nt = 0; nt < 8; nt++) {
                int gb = nt >> 1, ix = (nt & 1) * 2;
                mma_bf16(s[nt], qa_h[ks], bh[gb][ix], bh[gb][ix + 1]);
                mma_bf16(s[nt], qa_h[ks], bl[gb][ix], bl[gb][ix + 1]);
                mma_bf16(s[nt], qa_l[ks], bh[gb][ix], bh[gb][ix + 1]);
            }
        }

        // ---- online softmax (rows lane/4 and lane/4 + 8) ----
        float mx0 = -1e30f, mx1 = -1e30f;
        #pragma unroll
        for (int nt = 0; nt < 8; nt++) {
            #pragma unroll
            for (int q = 0; q < 4; q++) s[nt][q] *= SCALE;
            mx0 = fmaxf(mx0, fmaxf(s[nt][0], s[nt][1]));
            mx1 = fmaxf(mx1, fmaxf(s[nt][2], s[nt][3]));
        }
        mx0 = fmaxf(mx0, __shfl_xor_sync(0xffffffffu, mx0, 1));
        mx0 = fmaxf(mx0, __shfl_xor_sync(0xffffffffu, mx0, 2));
        mx1 = fmaxf(mx1, __shfl_xor_sync(0xffffffffu, mx1, 1));
        mx1 = fmaxf(mx1, __shfl_xor_sync(0xffffffffu, mx1, 2));

        float mn0 = fmaxf(m0, mx0), mn1 = fmaxf(m1, mx1);
        float c0 = __expf(m0 - mn0), c1 = __expf(m1 - mn1);
        float sum0 = 0.0f, sum1 = 0.0f;
        #pragma unroll
        for (int nt = 0; nt < 8; nt++) {
            s[nt][0] = __expf(s[nt][0] - mn0); sum0 += s[nt][0];
            s[nt][1] = __expf(s[nt][1] - mn0); sum0 += s[nt][1];
            s[nt][2] = __expf(s[nt][2] - mn1); sum1 += s[nt][2];
            s[nt][3] = __expf(s[nt][3] - mn1); sum1 += s[nt][3];
        }
        sum0 += __shfl_xor_sync(0xffffffffu, sum0, 1);
        sum0 += __shfl_xor_sync(0xffffffffu, sum0, 2);
        sum1 += __shfl_xor_sync(0xffffffffu, sum1, 1);
        sum1 += __shfl_xor_sync(0xffffffffu, sum1, 2);
        l0 = l0 * c0 + sum0;
        l1 = l1 * c1 + sum1;
        m0 = mn0; m1 = mn1;
        #pragma unroll
        for (int nt = 0; nt < 8; nt++) {
            O[nt][0] *= c0; O[nt][1] *= c0;
            O[nt][2] *= c1; O[nt][3] *= c1;
        }

        // ---- O += P @ V ----
        #pragma unroll
        for (int j = 0; j < 4; j++) {          // key16 step
            uint32_t pah[4], pal[4];
            split_pack(s[2 * j][0],     s[2 * j][1],     pah[0], pal[0]);
            split_pack(s[2 * j][2],     s[2 * j][3],     pah[1], pal[1]);
            split_pack(s[2 * j + 1][0], s[2 * j + 1][1], pah[2], pal[2]);
            split_pack(s[2 * j + 1][2], s[2 * j + 1][3], pah[3], pal[3]);

            uint32_t vhf[4][4], vlf[4][4];
            #pragma unroll
            for (int gv = 0; gv < 4; gv++) {
                uint32_t off = (uint32_t)(j * 16 + (g & 1) * 8 + row_in) * PDD
                             + (gv * 16 + (g >> 1) * 8) * 2;
                ldsm4t(sb + SVH + off, vhf[gv]);
                ldsm4t(sb + SVL + off, vlf[gv]);
            }
            #pragma unroll
            for (int nt = 0; nt < 8; nt++) {
                int gv = nt >> 1, ix = (nt & 1) * 2;
                mma_bf16(O[nt], pah, vhf[gv][ix], vhf[gv][ix + 1]);
                mma_bf16(O[nt], pah, vlf[gv][ix], vlf[gv][ix + 1]);
                mma_bf16(O[nt], pal, vhf[gv][ix], vhf[gv][ix + 1]);
            }
        }
        __syncthreads();   // protect K/V buffers before next load
    }

    // ---- epilogue: normalize, split to bf16 hi/lo ----
    float inv0 = 1.0f / (l0 + 1e-6f);
    float inv1 = 1.0f / (l1 + 1e-6f);
    int r0g = qrow0 + warp * 16 + (lane >> 2);
    #pragma unroll
    for (int nt = 0; nt < 8; nt++) {
        int col = h * DH_ + nt * 8 + (lane & 3) * 2;
        uint32_t h0, lo0, h1, lo1;
        split_pack(O[nt][0] * inv0, O[nt][1] * inv0, h0, lo0);
        split_pack(O[nt][2] * inv1, O[nt][3] * inv1, h1, lo1);
        *(uint32_t*)(g_ahi + (size_t)r0g * D_ + col) = h0;
        *(uint32_t*)(g_alo + (size_t)r0g * D_ + col) = lo0;
        *(uint32_t*)(g_ahi + (size_t)(r0g + 8) * D_ + col) = h1;
        *(uint32_t*)(g_alo + (size_t)(r0g + 8) * D_ + col) = lo1;
    }
}

// ---------------------------------------------------------------------------
// Launch
// ---------------------------------------------------------------------------
extern "C" void kernel_launch(void* const* d_in, const int* in_sizes, int n_in,
                              void* d_out, int out_size)
{
    const float* x    = (const float*)d_in[0];
    const float* Wqkv = (const float*)d_in[1];
    const float* Wout = (const float*)d_in[2];
    float* out = (float*)d_out;

    bf16 *xhi, *xlo, *wqhi, *wqlo, *wohi, *wolo, *qhi, *qlo, *ahi, *alo;
    cudaGetSymbolAddress((void**)&xhi,  g_xhi);
    cudaGetSymbolAddress((void**)&xlo,  g_xlo);
    cudaGetSymbolAddress((void**)&wqhi, g_wqhi);
    cudaGetSymbolAddress((void**)&wqlo, g_wqlo);
    cudaGetSymbolAddress((void**)&wohi, g_wohi);
    cudaGetSymbolAddress((void**)&wolo, g_wolo);
    cudaGetSymbolAddress((void**)&qhi,  g_qhi);
    cudaGetSymbolAddress((void**)&qlo,  g_qlo);
    cudaGetSymbolAddress((void**)&ahi,  g_ahi);
    cudaGetSymbolAddress((void**)&alo,  g_alo);

    cudaFuncSetAttribute(gemm_mma<true>,
                         cudaFuncAttributeMaxDynamicSharedMemorySize, 2 * GSTAGE);
    cudaFuncSetAttribute(gemm_mma<false>,
                         cudaFuncAttributeMaxDynamicSharedMemorySize, 2 * GSTAGE);
    cudaFuncSetAttribute(attn_mma,
                         cudaFuncAttributeMaxDynamicSharedMemorySize, ATT_SMEM);

    // 0) split inputs
    split_bf16<<<512, 256>>>(x,    xhi,  xlo,  M_TOT * D_);
    split_bf16<<<512, 256>>>(Wqkv, wqhi, wqlo, QKV_N * D_);
    split_bf16<<<256, 256>>>(Wout, wohi, wolo, D_ * D_);

    // 1) qkv = x @ Wqkv^T  -> bf16 hi/lo
    gemm_mma<true><<<dim3(QKV_N / 128, M_TOT / 128), 256, 2 * GSTAGE>>>(
        xhi, xlo, wqhi, wqlo, nullptr, qhi, qlo, QKV_N);

    // 2) attention -> g_ahi/g_alo
    attn_mma<<<dim3(S_ / 64, B_ * H_), 128, ATT_SMEM>>>();

    // 3) out = attn @ Wout^T -> fp32
    gemm_mma<false><<<dim3(D_ / 128, M_TOT / 128), 256, 2 * GSTAGE>>>(
        ahi, alo, wohi, wolo, out, nullptr, nullptr, D_);
}